// round 13
// baseline (speedup 1.0000x reference)
#include <cuda_runtime.h>
#include <cstdint>

// ---------------------------------------------------------------------------
// voxelization, scales (2,4,8,1). JIT/XLA-folded f32 quantization:
//   idx = trunc((p - lo) * RN(dims/(hi-lo))), folded consts exact: 5.0f, 10.0f
//   idx_s = idx_1 >> k exactly; idx may equal dims (boundary carries).
//   key = ((b*S+x)*S+y)*Z+z via ADDITION (carry-exact vs reference int64).
// Output: single FLOAT32 buffer, per scale:
//   full_coors [N,4] (b,x,y,z raw) | inv [N] | coors [M,4] (b,z,y,x)
// Dense bitmask + popcount prefix replaces sort/unique.
// R13: kout enum half writes through a 32KB smem stage (block-contiguous
//   ranks -> coalesced global stores); k1 drops the read-check for scale 1
//   (1.5% dup). kout per-point half and everything else unchanged from R12.
// ---------------------------------------------------------------------------

#define NMAX 2000000
// per-scale mask words padded past max carried key, in 8192-word blocks:
// scale2:65 scale4:9 scale8:2 scale1:513  (=589 blocks total)
#define TOTAL_WORDS 4825088   // 589*8192
#define NBLK_TOT 589
#define CHUNK_ROWS 2048       // smem staging rows (32KB)

__device__ unsigned  g_mask[TOTAL_WORDS];            // 19.3 MB bitmasks
__device__ uint4     g_mp4[TOTAL_WORDS / 2];         // 38.6 MB {mask,prefix}
__device__ unsigned  g_pt[NMAX];                     // 8 MB packed b,x1,y1,z1
__device__ unsigned long long g_stat[NBLK_TOT];      // lookback: flag<<32 | sum
__device__ long long g_bases[12];                    // ELEMENT offs: fc,inv,coors
__device__ int       g_is64;                         // batch INPUT width only
__device__ unsigned  g_ctr;                          // pscan completion counter

__constant__ int      c_k[4]    = {1, 2, 3, 0};
__constant__ unsigned c_woff[4] = {0u, 532480u, 606208u, 622592u};
__constant__ int      c_nb[4]   = {65, 9, 2, 513};
__constant__ int      c_sb[4]   = {0, 65, 74, 76};   // scale start block

__device__ __forceinline__ void blk2scale(unsigned bid, int& s, unsigned& lb) {
    if (bid < 65u)      { s = 0; lb = bid; }
    else if (bid < 74u) { s = 1; lb = bid - 65u; }
    else if (bid < 76u) { s = 2; lb = bid - 74u; }
    else                { s = 3; lb = bid - 76u; }
}

// word index -> scale (for kout's enumeration half)
__device__ __forceinline__ int word2scale(unsigned w) {
    return (w < 532480u) ? 0 : (w < 606208u) ? 1 : (w < 622592u) ? 2 : 3;
}

// ---------------- zero masks + lookback state + input-width detect
__global__ __launch_bounds__(256) void kzero(const unsigned* __restrict__ bat) {
    unsigned i = blockIdx.x * 256u + threadIdx.x;
    if (i < TOTAL_WORDS / 4) ((uint4*)g_mask)[i] = make_uint4(0u, 0u, 0u, 0u);
    if (blockIdx.x == 0) {
        for (int j = threadIdx.x; j < NBLK_TOT; j += 256) g_stat[j] = 0ull;
        if (threadIdx.x == 0) {
            g_ctr = 0u;
            unsigned acc = 0;
#pragma unroll
            for (int j = 1; j <= 16; j++) acc |= bat[2 * j + 1];
            g_is64 = (acc == 0u) ? 1 : 0;
        }
    }
}

// ---- pass 1: packed point + bitmask set + scale-2 full_coors (base 0)
__global__ __launch_bounds__(256) void k1(const float* __restrict__ pts,
                                          const void* __restrict__ bat,
                                          float* __restrict__ out, int n) {
    int i = blockIdx.x * 256 + threadIdx.x;
    if (i >= n) return;
    float px = pts[3 * i + 0];
    float py = pts[3 * i + 1];
    float pz = pts[3 * i + 2];
    unsigned b;
    if (g_is64) b = (unsigned)((const long long*)bat)[i];
    else        b = (unsigned)((const int*)bat)[i];
    // JIT/XLA-folded f32: trunc((p-lo) * const); consts exact. idx may == dims.
    unsigned x1 = (unsigned)(int)__fmul_rn(__fsub_rn(px, -51.2f), 5.0f);
    unsigned y1 = (unsigned)(int)__fmul_rn(__fsub_rn(py, -51.2f), 5.0f);
    unsigned z1 = (unsigned)(int)__fmul_rn(__fsub_rn(pz, -4.0f), 10.0f);
    g_pt[i] = (b << 27) | (x1 << 17) | (y1 << 7) | z1;   // raw, incl. boundary
    // scale-2 (s=0) full_coors: section base is statically 0
    *(float4*)(out + 4ll * i) = make_float4(
        (float)b, (float)(x1 >> 1), (float)(y1 >> 1), (float)(z1 >> 1));
#pragma unroll
    for (int s = 0; s < 4; s++) {
        int k = c_k[s], xb = 9 - k, zb = 6 - k;
        unsigned key = (((((b << xb) + (x1 >> k)) << xb) + (y1 >> k)) << zb)
                       + (z1 >> k);
        unsigned w = c_woff[s] + (key >> 5), bm = 1u << (key & 31);
        if (s == 3) {
            atomicOr(&g_mask[w], bm);   // scale 1: ~1.5% dup, check is waste
        } else {
            if (!(g_mask[w] & bm)) atomicOr(&g_mask[w], bm);
        }
    }
}

// block-wide inclusive scan of one value per thread (256 threads, 8 warps)
__device__ __forceinline__ unsigned blockscan256(unsigned v, unsigned* shw,
                                                 int tid) {
    unsigned x = v;
#pragma unroll
    for (int o = 1; o < 32; o <<= 1) {
        unsigned t = __shfl_up_sync(0xffffffffu, x, o);
        if ((tid & 31) >= o) x += t;
    }
    if ((tid & 31) == 31) shw[tid >> 5] = x;
    __syncthreads();
    if (tid < 8) {
        unsigned y = shw[tid];
#pragma unroll
        for (int o = 1; o < 8; o <<= 1) {
            unsigned t = __shfl_up_sync(0xffu, y, o);
            if (tid >= o) y += t;
        }
        shw[tid] = y;
    }
    __syncthreads();
    unsigned add = (tid >= 32) ? shw[(tid >> 5) - 1] : 0u;
    return x + add;
}

// ---- pscan: single-pass popcount scan (decoupled lookback, per scale) +
//      {mask,prefix} pair emission + section-base computation (last block).
__global__ __launch_bounds__(256) void pscan(int n) {
    int s; unsigned lb;
    blk2scale(blockIdx.x, s, lb);
    int tid = threadIdx.x;
    unsigned wbase = c_woff[s] + lb * 8192u + tid * 32u;
    const uint4* src = (const uint4*)(g_mask + wbase);
    unsigned sum = 0;
#pragma unroll
    for (int j = 0; j < 8; j++) {
        uint4 v = src[j];
        sum += __popc(v.x) + __popc(v.y) + __popc(v.z) + __popc(v.w);
    }
    __shared__ unsigned shw[8];
    unsigned incl = blockscan256(sum, shw, tid);
    __shared__ unsigned s_agg, s_base;
    if (tid == 255) s_agg = incl;
    __syncthreads();
    if (tid == 0) {
        unsigned agg = s_agg, excl = 0;
        if (lb == 0) {
            atomicExch(&g_stat[blockIdx.x], (2ull << 32) | agg);
        } else {
            atomicExch(&g_stat[blockIdx.x], (1ull << 32) | agg);
            int j = (int)blockIdx.x - 1;
            int sstart = (int)blockIdx.x - (int)lb;
            while (j >= sstart) {
                unsigned long long st;
                do { st = atomicAdd(&g_stat[j], 0ull); } while ((st >> 32) == 0ull);
                excl += (unsigned)st;
                if ((st >> 32) == 2ull) break;
                j--;
            }
            atomicExch(&g_stat[blockIdx.x], (2ull << 32) | (excl + agg));
        }
        s_base = excl;
    }
    __syncthreads();
    // emit {mask, prefix} pairs (mask reloaded, L1-resident)
    unsigned run = s_base + incl - sum;
    uint4* dst = (uint4*)((uint2*)g_mp4 + wbase);
#pragma unroll
    for (int j = 0; j < 8; j++) {
        uint4 v = src[j];
        unsigned r0 = run;
        unsigned r1 = r0 + __popc(v.x);
        unsigned r2 = r1 + __popc(v.y);
        unsigned r3 = r2 + __popc(v.z);
        run = r3 + __popc(v.w);
        dst[2 * j + 0] = make_uint4(v.x, r0, v.y, r1);
        dst[2 * j + 1] = make_uint4(v.z, r2, v.w, r3);
    }
    // last-arriving block computes output section bases
    __syncthreads();
    if (tid == 0) {
        __threadfence();
        if (atomicAdd(&g_ctr, 1u) == NBLK_TOT - 1u) {
            long long base2 = 0;  // float-element offsets into d_out
            for (int sc = 0; sc < 4; sc++) {
                int lastb = c_sb[sc] + c_nb[sc] - 1;
                unsigned Mtot = (unsigned)atomicAdd(&g_stat[lastb], 0ull);
                g_bases[3 * sc + 0] = base2;             // full_coors (4n)
                g_bases[3 * sc + 1] = base2 + 4ll * n;   // inv (n)
                g_bases[3 * sc + 2] = base2 + 5ll * n;   // coors (4M)
                base2 += 5ll * n + 4ll * (long long)Mtot;
            }
        }
    }
}

// ---- kout: blocks [0,nb2) = per-point outputs (fc s>0 + inv all scales);
//      blocks [nb2, ...)    = unique enumeration via smem stage. FLOAT32 out.
__global__ __launch_bounds__(256) void kout(float* __restrict__ out, int n,
                                            int nb2) {
    __shared__ float4  sbuf[CHUNK_ROWS];     // 32KB staging
    __shared__ unsigned sB0, sT;
    int tid = threadIdx.x;
    if ((int)blockIdx.x < nb2) {
        int i = blockIdx.x * 256 + tid;
        if (i >= n) return;
        unsigned r = g_pt[i];
        unsigned b  = r >> 27;
        unsigned x1 = (r >> 17) & 1023u;
        unsigned y1 = (r >> 7) & 1023u;
        unsigned z1 = r & 127u;
        // batch the 4 random gathers for MLP
        unsigned key[4];
#pragma unroll
        for (int s = 0; s < 4; s++) {
            int k = c_k[s], xb = 9 - k, zb = 6 - k;
            key[s] = (((((b << xb) + (x1 >> k)) << xb) + (y1 >> k)) << zb)
                     + (z1 >> k);
        }
        uint2 mp[4];
#pragma unroll
        for (int s = 0; s < 4; s++)
            mp[s] = ((const uint2*)g_mp4)[c_woff[s] + (key[s] >> 5)];
#pragma unroll
        for (int s = 0; s < 4; s++) {
            int k = c_k[s];
            unsigned inv = mp[s].y +
                __popc(mp[s].x & ((1u << (key[s] & 31)) - 1u));
            if (s > 0) {   // s==0 full_coors already written by k1
                float* fc = out + g_bases[3 * s + 0] + 4ll * i;
                *(float4*)fc = make_float4((float)b, (float)(x1 >> k),
                                           (float)(y1 >> k), (float)(z1 >> k));
            }
            out[g_bases[3 * s + 1] + i] = (float)inv;
        }
    } else {
        unsigned w = (blockIdx.x - nb2) * 256u + tid;   // one word per thread
        uint2 mp = ((const uint2*)g_mp4)[w];
        int s = word2scale(w);
        int k = c_k[s], xb = 9 - k, zb = 6 - k;
        if (tid == 0) sB0 = mp.y;
        if (tid == 255) sT = mp.y + (unsigned)__popc(mp.x);
        __syncthreads();
        unsigned B0 = sB0;
        unsigned T = sT - B0;                 // total rows in this block
        if (T == 0) return;
        unsigned lr0 = mp.y - B0;             // this thread's first local rank
        unsigned wk = (w - c_woff[s]) << 5;
        float* cb = out + g_bases[3 * s + 2];
        for (unsigned start = 0; start < T; start += CHUNK_ROWS) {
            unsigned end = start + CHUNK_ROWS;
            // enumerate this word's bits whose local rank falls in the window
            unsigned m = mp.x, lr = lr0;
            if (lr0 < end && lr0 + (unsigned)__popc(mp.x) > start) {
                while (m) {
                    int bit = __ffs(m) - 1;
                    m &= m - 1;
                    if (lr >= end) break;
                    if (lr >= start) {
                        unsigned keyv = wk | (unsigned)bit;
                        unsigned z = keyv & ((1u << zb) - 1);
                        unsigned y = (keyv >> zb) & ((1u << xb) - 1);
                        unsigned x = (keyv >> (zb + xb)) & ((1u << xb) - 1);
                        unsigned bb = keyv >> (zb + 2 * xb);
                        sbuf[lr - start] = make_float4(
                            (float)bb, (float)z, (float)y, (float)x);
                    }
                    lr++;
                }
            }
            __syncthreads();
            unsigned rows = min((unsigned)CHUNK_ROWS, T - start);
            float4* gdst = (float4*)(cb + 4ull * (B0 + start));
            for (unsigned rr = tid; rr < rows; rr += 256)
                gdst[rr] = sbuf[rr];
            __syncthreads();
        }
    }
}

// ---------------------------------------------------------------------------
extern "C" void kernel_launch(void* const* d_in, const int* in_sizes, int n_in,
                              void* d_out, int out_size) {
    // order auto-detect: points has 3x the elements of batch_idx
    const float* pts;
    const void*  bat;
    int n;
    if ((long long)in_sizes[0] == 3ll * in_sizes[1]) {
        pts = (const float*)d_in[0]; bat = d_in[1]; n = in_sizes[1];
    } else {
        pts = (const float*)d_in[1]; bat = d_in[0]; n = in_sizes[0];
    }

    kzero<<<(TOTAL_WORDS / 4 + 255) / 256, 256>>>((const unsigned*)bat);
    k1<<<(n + 255) / 256, 256>>>(pts, bat, (float*)d_out, n);
    pscan<<<NBLK_TOT, 256>>>(n);
    int nb2 = (n + 255) / 256;
    int nb3 = TOTAL_WORDS / 256;
    kout<<<nb2 + nb3, 256>>>((float*)d_out, n, nb2);
}

// round 14
// speedup vs baseline: 1.4434x; 1.4434x over previous
#include <cuda_runtime.h>
#include <cstdint>

// ---------------------------------------------------------------------------
// voxelization, scales (2,4,8,1). JIT/XLA-folded f32 quantization:
//   idx = trunc((p - lo) * RN(dims/(hi-lo))), folded consts exact: 5.0f, 10.0f
//   idx_s = idx_1 >> k exactly; idx may equal dims (boundary carries).
//   key = ((b*S+x)*S+y)*Z+z via ADDITION (carry-exact vs reference int64).
// Output: single FLOAT32 buffer, per scale:
//   full_coors [N,4] (b,x,y,z raw) | inv [N] | coors [M,4] (b,z,y,x)
// Dense bitmask + popcount prefix replaces sort/unique.
// R14: revert R13's smem staging (regression). k1 atomic policy from dup-rate
//   math: fire-and-forget RED.OR for scales 2/4/1 (dup 6%/35%/1.5%),
//   read-check only for scale 8 (dup 87%, hot words).
// ---------------------------------------------------------------------------

#define NMAX 2000000
// per-scale mask words padded past max carried key, in 8192-word blocks:
// scale2:65 scale4:9 scale8:2 scale1:513  (=589 blocks total)
#define TOTAL_WORDS 4825088   // 589*8192
#define NBLK_TOT 589

__device__ unsigned  g_mask[TOTAL_WORDS];            // 19.3 MB bitmasks
__device__ uint4     g_mp4[TOTAL_WORDS / 2];         // 38.6 MB {mask,prefix}
__device__ unsigned  g_pt[NMAX];                     // 8 MB packed b,x1,y1,z1
__device__ unsigned long long g_stat[NBLK_TOT];      // lookback: flag<<32 | sum
__device__ long long g_bases[12];                    // ELEMENT offs: fc,inv,coors
__device__ int       g_is64;                         // batch INPUT width only
__device__ unsigned  g_ctr;                          // pscan completion counter

__constant__ int      c_k[4]    = {1, 2, 3, 0};
__constant__ unsigned c_woff[4] = {0u, 532480u, 606208u, 622592u};
__constant__ int      c_nb[4]   = {65, 9, 2, 513};
__constant__ int      c_sb[4]   = {0, 65, 74, 76};   // scale start block

__device__ __forceinline__ void blk2scale(unsigned bid, int& s, unsigned& lb) {
    if (bid < 65u)      { s = 0; lb = bid; }
    else if (bid < 74u) { s = 1; lb = bid - 65u; }
    else if (bid < 76u) { s = 2; lb = bid - 74u; }
    else                { s = 3; lb = bid - 76u; }
}

// word index -> scale (for kout's enumeration half)
__device__ __forceinline__ int word2scale(unsigned w) {
    return (w < 532480u) ? 0 : (w < 606208u) ? 1 : (w < 622592u) ? 2 : 3;
}

// ---------------- zero masks + lookback state + input-width detect
__global__ __launch_bounds__(256) void kzero(const unsigned* __restrict__ bat) {
    unsigned i = blockIdx.x * 256u + threadIdx.x;
    if (i < TOTAL_WORDS / 4) ((uint4*)g_mask)[i] = make_uint4(0u, 0u, 0u, 0u);
    if (blockIdx.x == 0) {
        for (int j = threadIdx.x; j < NBLK_TOT; j += 256) g_stat[j] = 0ull;
        if (threadIdx.x == 0) {
            g_ctr = 0u;
            unsigned acc = 0;
#pragma unroll
            for (int j = 1; j <= 16; j++) acc |= bat[2 * j + 1];
            g_is64 = (acc == 0u) ? 1 : 0;
        }
    }
}

// ---- pass 1: packed point + bitmask set + scale-2 full_coors (base 0)
__global__ __launch_bounds__(256) void k1(const float* __restrict__ pts,
                                          const void* __restrict__ bat,
                                          float* __restrict__ out, int n) {
    int i = blockIdx.x * 256 + threadIdx.x;
    if (i >= n) return;
    float px = pts[3 * i + 0];
    float py = pts[3 * i + 1];
    float pz = pts[3 * i + 2];
    unsigned b;
    if (g_is64) b = (unsigned)((const long long*)bat)[i];
    else        b = (unsigned)((const int*)bat)[i];
    // JIT/XLA-folded f32: trunc((p-lo) * const); consts exact. idx may == dims.
    unsigned x1 = (unsigned)(int)__fmul_rn(__fsub_rn(px, -51.2f), 5.0f);
    unsigned y1 = (unsigned)(int)__fmul_rn(__fsub_rn(py, -51.2f), 5.0f);
    unsigned z1 = (unsigned)(int)__fmul_rn(__fsub_rn(pz, -4.0f), 10.0f);
    g_pt[i] = (b << 27) | (x1 << 17) | (y1 << 7) | z1;   // raw, incl. boundary
    // scale-2 (s=0) full_coors: section base is statically 0
    *(float4*)(out + 4ll * i) = make_float4(
        (float)b, (float)(x1 >> 1), (float)(y1 >> 1), (float)(z1 >> 1));
#pragma unroll
    for (int s = 0; s < 4; s++) {
        int k = c_k[s], xb = 9 - k, zb = 6 - k;
        unsigned key = (((((b << xb) + (x1 >> k)) << xb) + (y1 >> k)) << zb)
                       + (z1 >> k);
        unsigned w = c_woff[s] + (key >> 5), bm = 1u << (key & 31);
        if (s == 2) {
            // scale 8: 87% dup on 1MB of hot words -> read-check elides atomics
            if (!(g_mask[w] & bm)) atomicOr(&g_mask[w], bm);
        } else {
            atomicOr(&g_mask[w], bm);   // dup 6%/35%/1.5%: check is net waste
        }
    }
}

// block-wide inclusive scan of one value per thread (256 threads, 8 warps)
__device__ __forceinline__ unsigned blockscan256(unsigned v, unsigned* shw,
                                                 int tid) {
    unsigned x = v;
#pragma unroll
    for (int o = 1; o < 32; o <<= 1) {
        unsigned t = __shfl_up_sync(0xffffffffu, x, o);
        if ((tid & 31) >= o) x += t;
    }
    if ((tid & 31) == 31) shw[tid >> 5] = x;
    __syncthreads();
    if (tid < 8) {
        unsigned y = shw[tid];
#pragma unroll
        for (int o = 1; o < 8; o <<= 1) {
            unsigned t = __shfl_up_sync(0xffu, y, o);
            if (tid >= o) y += t;
        }
        shw[tid] = y;
    }
    __syncthreads();
    unsigned add = (tid >= 32) ? shw[(tid >> 5) - 1] : 0u;
    return x + add;
}

// ---- pscan: single-pass popcount scan (decoupled lookback, per scale) +
//      {mask,prefix} pair emission + section-base computation (last block).
__global__ __launch_bounds__(256) void pscan(int n) {
    int s; unsigned lb;
    blk2scale(blockIdx.x, s, lb);
    int tid = threadIdx.x;
    unsigned wbase = c_woff[s] + lb * 8192u + tid * 32u;
    const uint4* src = (const uint4*)(g_mask + wbase);
    unsigned sum = 0;
#pragma unroll
    for (int j = 0; j < 8; j++) {
        uint4 v = src[j];
        sum += __popc(v.x) + __popc(v.y) + __popc(v.z) + __popc(v.w);
    }
    __shared__ unsigned shw[8];
    unsigned incl = blockscan256(sum, shw, tid);
    __shared__ unsigned s_agg, s_base;
    if (tid == 255) s_agg = incl;
    __syncthreads();
    if (tid == 0) {
        unsigned agg = s_agg, excl = 0;
        if (lb == 0) {
            atomicExch(&g_stat[blockIdx.x], (2ull << 32) | agg);
        } else {
            atomicExch(&g_stat[blockIdx.x], (1ull << 32) | agg);
            int j = (int)blockIdx.x - 1;
            int sstart = (int)blockIdx.x - (int)lb;
            while (j >= sstart) {
                unsigned long long st;
                do { st = atomicAdd(&g_stat[j], 0ull); } while ((st >> 32) == 0ull);
                excl += (unsigned)st;
                if ((st >> 32) == 2ull) break;
                j--;
            }
            atomicExch(&g_stat[blockIdx.x], (2ull << 32) | (excl + agg));
        }
        s_base = excl;
    }
    __syncthreads();
    // emit {mask, prefix} pairs (mask reloaded, L1-resident)
    unsigned run = s_base + incl - sum;
    uint4* dst = (uint4*)((uint2*)g_mp4 + wbase);
#pragma unroll
    for (int j = 0; j < 8; j++) {
        uint4 v = src[j];
        unsigned r0 = run;
        unsigned r1 = r0 + __popc(v.x);
        unsigned r2 = r1 + __popc(v.y);
        unsigned r3 = r2 + __popc(v.z);
        run = r3 + __popc(v.w);
        dst[2 * j + 0] = make_uint4(v.x, r0, v.y, r1);
        dst[2 * j + 1] = make_uint4(v.z, r2, v.w, r3);
    }
    // last-arriving block computes output section bases
    __syncthreads();
    if (tid == 0) {
        __threadfence();
        if (atomicAdd(&g_ctr, 1u) == NBLK_TOT - 1u) {
            long long base2 = 0;  // float-element offsets into d_out
            for (int sc = 0; sc < 4; sc++) {
                int lastb = c_sb[sc] + c_nb[sc] - 1;
                unsigned Mtot = (unsigned)atomicAdd(&g_stat[lastb], 0ull);
                g_bases[3 * sc + 0] = base2;             // full_coors (4n)
                g_bases[3 * sc + 1] = base2 + 4ll * n;   // inv (n)
                g_bases[3 * sc + 2] = base2 + 5ll * n;   // coors (4M)
                base2 += 5ll * n + 4ll * (long long)Mtot;
            }
        }
    }
}

// ---- kout: blocks [0,nb2) = per-point outputs (fc s>0 + inv all scales);
//      blocks [nb2, ...)    = unique enumeration (coors). FLOAT32 out.
__global__ __launch_bounds__(256) void kout(float* __restrict__ out, int n,
                                            int nb2) {
    if ((int)blockIdx.x < nb2) {
        int i = blockIdx.x * 256 + threadIdx.x;
        if (i >= n) return;
        unsigned r = g_pt[i];
        unsigned b  = r >> 27;
        unsigned x1 = (r >> 17) & 1023u;
        unsigned y1 = (r >> 7) & 1023u;
        unsigned z1 = r & 127u;
        // batch the 4 random gathers for MLP
        unsigned key[4];
#pragma unroll
        for (int s = 0; s < 4; s++) {
            int k = c_k[s], xb = 9 - k, zb = 6 - k;
            key[s] = (((((b << xb) + (x1 >> k)) << xb) + (y1 >> k)) << zb)
                     + (z1 >> k);
        }
        uint2 mp[4];
#pragma unroll
        for (int s = 0; s < 4; s++)
            mp[s] = ((const uint2*)g_mp4)[c_woff[s] + (key[s] >> 5)];
#pragma unroll
        for (int s = 0; s < 4; s++) {
            int k = c_k[s];
            unsigned inv = mp[s].y +
                __popc(mp[s].x & ((1u << (key[s] & 31)) - 1u));
            if (s > 0) {   // s==0 full_coors already written by k1
                float* fc = out + g_bases[3 * s + 0] + 4ll * i;
                *(float4*)fc = make_float4((float)b, (float)(x1 >> k),
                                           (float)(y1 >> k), (float)(z1 >> k));
            }
            out[g_bases[3 * s + 1] + i] = (float)inv;
        }
    } else {
        unsigned w = (blockIdx.x - nb2) * 256u + threadIdx.x;
        if (w >= TOTAL_WORDS) return;
        uint2 mp = ((const uint2*)g_mp4)[w];
        unsigned m = mp.x;
        if (!m) return;
        int s = word2scale(w);
        long long pr = (long long)mp.y;
        long long cob = g_bases[3 * s + 2];
        int k = c_k[s], xb = 9 - k, zb = 6 - k;
        unsigned wk = (w - c_woff[s]) << 5;
        while (m) {
            int bit = __ffs(m) - 1;
            m &= m - 1;
            unsigned key = wk | (unsigned)bit;
            unsigned z = key & ((1u << zb) - 1);
            unsigned y = (key >> zb) & ((1u << xb) - 1);
            unsigned x = (key >> (zb + xb)) & ((1u << xb) - 1);
            unsigned b = key >> (zb + 2 * xb);
            *(float4*)(out + cob + 4ll * pr) =
                make_float4((float)b, (float)z, (float)y, (float)x);
            pr++;
        }
    }
}

// ---------------------------------------------------------------------------
extern "C" void kernel_launch(void* const* d_in, const int* in_sizes, int n_in,
                              void* d_out, int out_size) {
    // order auto-detect: points has 3x the elements of batch_idx
    const float* pts;
    const void*  bat;
    int n;
    if ((long long)in_sizes[0] == 3ll * in_sizes[1]) {
        pts = (const float*)d_in[0]; bat = d_in[1]; n = in_sizes[1];
    } else {
        pts = (const float*)d_in[1]; bat = d_in[0]; n = in_sizes[0];
    }

    kzero<<<(TOTAL_WORDS / 4 + 255) / 256, 256>>>((const unsigned*)bat);
    k1<<<(n + 255) / 256, 256>>>(pts, bat, (float*)d_out, n);
    pscan<<<NBLK_TOT, 256>>>(n);
    int nb2 = (n + 255) / 256;
    int nb3 = (TOTAL_WORDS + 255) / 256;
    kout<<<nb2 + nb3, 256>>>((float*)d_out, n, nb2);
}